// round 5
// baseline (speedup 1.0000x reference)
#include <cuda_runtime.h>
#include <cstdint>
#include <cstddef>

#define M_MSG 131072
#define NNODE 65536
#define HID   256
#define DEPTH 6
#define NTREE 2048

// ---------------- static device scratch (allocation-free kernel_launch) ----
__device__ float g_XC[(size_t)M_MSG * 768];   // [xz | xh | r1+Ur_b] per message
__device__ float g_U [(size_t)M_MSG * 512];   // [h@Ur | h@Wzh] per message
__device__ float g_h [(size_t)M_MSG * HID];
__device__ float g_zb[(size_t)M_MSG * HID];   // z gate
__device__ float g_t1[(size_t)M_MSG * HID];   // (1-z)*sum_h
__device__ float g_sg[(size_t)M_MSG * HID];   // sum_gh
__device__ float g_mn[(size_t)NNODE * HID];   // mess_nei
__device__ float g_nv[(size_t)NNODE * HID];   // node_vec
__device__ float g_B0[256 * 768];             // [Wzx | Whx | Wr]
__device__ float g_B1[256 * 512];             // [Ur | Wzh]
__device__ float g_b0[768];                   // [Wz_b | Wh_b | Ur_b]
__device__ int   g_mx[M_MSG];                 // fnode[fmess[m]]

// ---------------- small helpers -------------------------------------------
__global__ void k_zero(float* p, int n) {
    int i = blockIdx.x * blockDim.x + threadIdx.x;
    if (i < n) p[i] = 0.f;
}

__global__ void k_pack(const float* __restrict__ Wz, const float* __restrict__ Wh,
                       const float* __restrict__ Wr, const float* __restrict__ Ur,
                       const float* __restrict__ Wzb, const float* __restrict__ Whb,
                       const float* __restrict__ Urb,
                       const int* __restrict__ fnode, const int* __restrict__ fmess,
                       float* __restrict__ B0, float* __restrict__ B1,
                       float* __restrict__ b0, int* __restrict__ mx) {
    int i = blockIdx.x * blockDim.x + threadIdx.x;
    int st = gridDim.x * blockDim.x;
    for (int t = i; t < 256 * 768; t += st) {
        int k = t / 768, j = t - k * 768;
        B0[t] = (j < 256) ? Wz[k * 256 + j]
              : (j < 512) ? Wh[k * 256 + (j - 256)]
                          : Wr[k * 256 + (j - 512)];
    }
    for (int t = i; t < 256 * 512; t += st) {
        int k = t / 512, j = t - k * 512;
        B1[t] = (j < 256) ? Ur[k * 256 + j]
                          : Wz[(256 + k) * 256 + (j - 256)];
    }
    for (int t = i; t < 768; t += st)
        b0[t] = (t < 256) ? Wzb[t] : (t < 512) ? Whb[t - 256] : Urb[t - 512];
    for (int t = i; t < M_MSG; t += st) mx[t] = fnode[fmess[t]];
}

__device__ __forceinline__ float sgm(float x) { return 1.0f / (1.0f + __expf(-x)); }

// Per-message neighbor gather + r/z gates. 64 threads per message (float4 lanes).
__global__ void k_gather(const int* __restrict__ mg, const float* __restrict__ h,
                         const float* __restrict__ U, const float* __restrict__ XC,
                         float* __restrict__ zp, float* __restrict__ t1p,
                         float* __restrict__ sgp) {
    int gt = blockIdx.x * blockDim.x + threadIdx.x;
    int msg = gt >> 6;
    int j = gt & 63;
    if (msg >= M_MSG) return;
    const float4* h4 = (const float4*)h;   // row stride 64
    const float4* U4 = (const float4*)U;   // row stride 128
    const float4* X4 = (const float4*)XC;  // row stride 192
    float4 xz = X4[(size_t)msg * 192 + j];
    float4 r1 = X4[(size_t)msg * 192 + 128 + j];
    float shx = 0, shy = 0, shz = 0, shw = 0;
    float zlx = xz.x, zly = xz.y, zlz = xz.z, zlw = xz.w;
    float sgx = 0, sgy = 0, sgz = 0, sgw = 0;
#pragma unroll
    for (int k = 0; k < 5; k++) {
        int gi = mg[msg * 5 + k];
        float4 hv = h4[(size_t)gi * 64 + j];
        float4 uh = U4[(size_t)gi * 128 + j];
        float4 hz = U4[(size_t)gi * 128 + 64 + j];
        shx += hv.x; shy += hv.y; shz += hv.z; shw += hv.w;
        zlx += hz.x; zly += hz.y; zlz += hz.z; zlw += hz.w;
        sgx += sgm(r1.x + uh.x) * hv.x;
        sgy += sgm(r1.y + uh.y) * hv.y;
        sgz += sgm(r1.z + uh.z) * hv.z;
        sgw += sgm(r1.w + uh.w) * hv.w;
    }
    float zx = sgm(zlx), zy = sgm(zly), zz2 = sgm(zlz), zw = sgm(zlw);
    size_t o = (size_t)msg * 64 + j;
    ((float4*)zp)[o]  = make_float4(zx, zy, zz2, zw);
    ((float4*)t1p)[o] = make_float4((1.f - zx) * shx, (1.f - zy) * shy,
                                    (1.f - zz2) * shz, (1.f - zw) * shw);
    ((float4*)sgp)[o] = make_float4(sgx, sgy, sgz, sgw);
}

// Per-node neighbor-message sum.
__global__ void k_gnode(const int* __restrict__ ng, const float* __restrict__ h,
                        float* __restrict__ mn) {
    int gt = blockIdx.x * blockDim.x + threadIdx.x;
    int n = gt >> 6;
    int j = gt & 63;
    if (n >= NNODE) return;
    const float4* h4 = (const float4*)h;
    float x = 0, y = 0, z = 0, w = 0;
#pragma unroll
    for (int k = 0; k < 5; k++) {
        int gi = ng[n * 5 + k];
        float4 hv = h4[(size_t)gi * 64 + j];
        x += hv.x; y += hv.y; z += hv.z; w += hv.w;
    }
    ((float4*)mn)[(size_t)n * 64 + j] = make_float4(x, y, z, w);
}

// Deterministic segment mean over sorted scope_ids. One block per tree.
__global__ void k_seg(const int* __restrict__ scope, const float* __restrict__ nv,
                      float* __restrict__ out) {
    int t = blockIdx.x;
    int j = threadIdx.x;
    int lo = 0, hi = NNODE;
    while (lo < hi) { int mid = (lo + hi) >> 1; if (scope[mid] < t) lo = mid + 1; else hi = mid; }
    int lo2 = lo, hi2 = NNODE;
    while (lo2 < hi2) { int mid = (lo2 + hi2) >> 1; if (scope[mid] < t + 1) lo2 = mid + 1; else hi2 = mid; }
    float s = 0.f;
    for (int r = lo; r < lo2; r++) s += nv[(size_t)r * HID + j];
    out[(size_t)t * HID + j] = s / fmaxf((float)(lo2 - lo), 1.f);
}

// ---------------- fp32 SGEMM, 128x128x16 tiles, 8x8 register microtiles ----
// MODE 0: A row = emb[aidx[m]], +bias, store C            (XC precompute)
// MODE 1: plain A @ B store                               (U = h @ [Ur|Wzh])
// MODE 2: GRU combine epilogue, in-place h update         (P = sum_gh @ Whh)
// MODE 3: A row = [emb[aidx[n]] | A2[n]] (K=512), +bias, relu, store (node_vec)
struct GP {
    const float* A; const float* B; float* C;
    int M, N, K;
    const float* bias;
    const int* aidx; const float* emb;
    const float* A2;
    const float* XC;
    const float* zv; const float* t1;
};

template <int MODE>
__global__ void __launch_bounds__(256, 2) sgemm(GP p) {
    constexpr int BM = 128, BN = 128, BK = 16;
    __shared__ float As[2][BK][BM + 4];
    __shared__ float Bs[2][BK][BN];
    int tid = threadIdx.x;
    int m0 = blockIdx.y * BM, n0 = blockIdx.x * BN;
    int tc = tid & 15, tr = tid >> 4;
    int akq = (tid & 3) * 4;
    int bk0 = tid >> 5;
    int bcol = (tid & 31) * 4;

    int arow[2];
    const float* ab1[2];
    const float* ab2[2];
#pragma unroll
    for (int u = 0; u < 2; u++) {
        arow[u] = (tid + u * 256) >> 2;
        int m = m0 + arow[u];
        if (MODE == 0) {
            ab1[u] = p.emb + (size_t)p.aidx[m] * 256; ab2[u] = ab1[u];
        } else if (MODE == 3) {
            ab1[u] = p.emb + (size_t)p.aidx[m] * 256;
            ab2[u] = p.A2 + (size_t)m * 256;
        } else {
            ab1[u] = p.A + (size_t)m * p.K; ab2[u] = ab1[u];
        }
    }

    float4 aR[2], bR[2];
    auto loadg = [&](int s) {
        int k0 = s * BK;
#pragma unroll
        for (int u = 0; u < 2; u++) {
            int k = k0 + akq;
            const float* src = ab1[u] + k;
            if (MODE == 3 && k >= 256) src = ab2[u] + (k - 256);
            aR[u] = *(const float4*)src;
            bR[u] = *(const float4*)(p.B + (size_t)(k0 + bk0 + u * 8) * p.N + n0 + bcol);
        }
    };
    auto stos = [&](int buf) {
#pragma unroll
        for (int u = 0; u < 2; u++) {
            As[buf][akq + 0][arow[u]] = aR[u].x;
            As[buf][akq + 1][arow[u]] = aR[u].y;
            As[buf][akq + 2][arow[u]] = aR[u].z;
            As[buf][akq + 3][arow[u]] = aR[u].w;
            *(float4*)&Bs[buf][bk0 + u * 8][bcol] = bR[u];
        }
    };

    float acc[8][8];
#pragma unroll
    for (int i = 0; i < 8; i++)
#pragma unroll
        for (int jj = 0; jj < 8; jj++) acc[i][jj] = 0.f;

    int nsteps = p.K / BK;
    loadg(0); stos(0); __syncthreads();
    for (int s = 0; s < nsteps; s++) {
        int buf = s & 1;
        if (s + 1 < nsteps) loadg(s + 1);
#pragma unroll
        for (int kk = 0; kk < BK; kk++) {
            float4 a0 = *(const float4*)&As[buf][kk][tr * 8];
            float4 a1 = *(const float4*)&As[buf][kk][tr * 8 + 4];
            float4 b0 = *(const float4*)&Bs[buf][kk][tc * 8];
            float4 b1 = *(const float4*)&Bs[buf][kk][tc * 8 + 4];
            float a[8] = {a0.x, a0.y, a0.z, a0.w, a1.x, a1.y, a1.z, a1.w};
            float b[8] = {b0.x, b0.y, b0.z, b0.w, b1.x, b1.y, b1.z, b1.w};
#pragma unroll
            for (int i = 0; i < 8; i++)
#pragma unroll
                for (int jj = 0; jj < 8; jj++)
                    acc[i][jj] = fmaf(a[i], b[jj], acc[i][jj]);
        }
        if (s + 1 < nsteps) stos(buf ^ 1);
        __syncthreads();
    }

#pragma unroll
    for (int i = 0; i < 8; i++) {
        int m = m0 + tr * 8 + i;
#pragma unroll
        for (int v = 0; v < 2; v++) {
            int c = n0 + tc * 8 + v * 4;
            float4 r = make_float4(acc[i][v * 4], acc[i][v * 4 + 1],
                                   acc[i][v * 4 + 2], acc[i][v * 4 + 3]);
            if (MODE == 0 || MODE == 3) {
                r.x += p.bias[c];     r.y += p.bias[c + 1];
                r.z += p.bias[c + 2]; r.w += p.bias[c + 3];
                if (MODE == 3) {
                    r.x = fmaxf(r.x, 0.f); r.y = fmaxf(r.y, 0.f);
                    r.z = fmaxf(r.z, 0.f); r.w = fmaxf(r.w, 0.f);
                }
                *(float4*)&p.C[(size_t)m * p.N + c] = r;
            } else if (MODE == 1) {
                *(float4*)&p.C[(size_t)m * p.N + c] = r;
            } else {  // MODE 2: h = (t1 + z * tanh(xh + P)) * mask
                size_t o = (size_t)m * HID + c;
                float4 xh = *(const float4*)&p.XC[(size_t)m * 768 + 256 + c];
                float4 zz = *(const float4*)&p.zv[o];
                float4 t1 = *(const float4*)&p.t1[o];
                float4 hn;
                hn.x = t1.x + zz.x * tanhf(xh.x + r.x);
                hn.y = t1.y + zz.y * tanhf(xh.y + r.y);
                hn.z = t1.z + zz.z * tanhf(xh.z + r.z);
                hn.w = t1.w + zz.w * tanhf(xh.w + r.w);
                if (m == 0) hn = make_float4(0.f, 0.f, 0.f, 0.f);
                *(float4*)&p.C[o] = hn;
            }
        }
    }
}

// ---------------- orchestration --------------------------------------------
extern "C" void kernel_launch(void* const* d_in, const int* in_sizes, int n_in,
                              void* d_out, int out_size) {
    const int*   fnode = (const int*)d_in[0];
    const int*   fmess = (const int*)d_in[1];
    const int*   ng    = (const int*)d_in[2];
    const int*   mg    = (const int*)d_in[3];
    const int*   scope = (const int*)d_in[4];
    const float* emb   = (const float*)d_in[5];
    const float* Wz    = (const float*)d_in[6];
    const float* Wzb   = (const float*)d_in[7];
    const float* Wr    = (const float*)d_in[8];
    const float* Ur    = (const float*)d_in[9];
    const float* Urb   = (const float*)d_in[10];
    const float* Wh    = (const float*)d_in[11];
    const float* Whb   = (const float*)d_in[12];
    const float* Ow    = (const float*)d_in[13];
    const float* Ob    = (const float*)d_in[14];
    float* out = (float*)d_out;

    float *XC, *U, *h, *z, *t1, *sg, *mn, *nv, *B0, *B1, *b0; int* mx;
    cudaGetSymbolAddress((void**)&XC, g_XC);
    cudaGetSymbolAddress((void**)&U,  g_U);
    cudaGetSymbolAddress((void**)&h,  g_h);
    cudaGetSymbolAddress((void**)&z,  g_zb);
    cudaGetSymbolAddress((void**)&t1, g_t1);
    cudaGetSymbolAddress((void**)&sg, g_sg);
    cudaGetSymbolAddress((void**)&mn, g_mn);
    cudaGetSymbolAddress((void**)&nv, g_nv);
    cudaGetSymbolAddress((void**)&B0, g_B0);
    cudaGetSymbolAddress((void**)&B1, g_B1);
    cudaGetSymbolAddress((void**)&b0, g_b0);
    cudaGetSymbolAddress((void**)&mx, g_mx);

    int nh = M_MSG * HID;
    k_zero<<<(nh + 255) / 256, 256>>>(h, nh);
    k_pack<<<1024, 256>>>(Wz, Wh, Wr, Ur, Wzb, Whb, Urb, fnode, fmess, B0, B1, b0, mx);

    // XC = x @ [Wzx|Whx|Wr] + [bz|bh|Ur_b], x gathered from emb on the fly
    GP p0{}; p0.B = B0; p0.C = XC; p0.M = M_MSG; p0.N = 768; p0.K = 256;
    p0.bias = b0; p0.aidx = mx; p0.emb = emb;
    sgemm<0><<<dim3(6, M_MSG / 128), 256>>>(p0);

    for (int d = 0; d < DEPTH; d++) {
        // U = h @ [Ur | Wzh]
        GP p1{}; p1.A = h; p1.B = B1; p1.C = U; p1.M = M_MSG; p1.N = 512; p1.K = 256;
        sgemm<1><<<dim3(4, M_MSG / 128), 256>>>(p1);
        // neighbor gather + r/z gates
        k_gather<<<(M_MSG * 64) / 256, 256>>>(mg, h, U, XC, z, t1, sg);
        // P = sum_gh @ Whh ; h = (t1 + z*tanh(xh+P)) * mask  (in-place h)
        GP p2{}; p2.A = sg; p2.B = Wh + 256 * 256; p2.C = h;
        p2.M = M_MSG; p2.N = 256; p2.K = 256;
        p2.XC = XC; p2.zv = z; p2.t1 = t1;
        sgemm<2><<<dim3(2, M_MSG / 128), 256>>>(p2);
    }

    // mess_nei per node
    k_gnode<<<(NNODE * 64) / 256, 256>>>(ng, h, mn);

    // node_vec = relu([x_node | mess_nei] @ out_w + out_b)
    GP p3{}; p3.B = Ow; p3.C = nv; p3.M = NNODE; p3.N = 256; p3.K = 512;
    p3.bias = Ob; p3.aidx = fnode; p3.emb = emb; p3.A2 = mn;
    sgemm<3><<<dim3(2, NNODE / 128), 256>>>(p3);

    // segment mean (sorted scopes, deterministic)
    k_seg<<<NTREE, 256>>>(scope, nv, out);
}

// round 7
// speedup vs baseline: 1.1042x; 1.1042x over previous
#include <cuda_runtime.h>
#include <cuda_bf16.h>
#include <cstdint>
#include <cstddef>

#define M_MSG 131072
#define NNODE 65536
#define HID   256
#define DEPTH 6
#define NTREE 2048

// tcgen05 is only available on arch-accelerated targets (sm_103a/sm_100a).
// The harness also runs a plain compute_103 PTX pass; give it an FFMA fallback.
#if defined(__CUDA_ARCH_FEAT_SM103_ALL) || defined(__CUDA_ARCH_FEAT_SM100_ALL) || \
    defined(__CUDA_ARCH_FEAT_SM101_ALL) || defined(__CUDA_ARCH_FEAT_SM110_ALL)
#define TC_OK 1
#else
#define TC_OK 0
#endif

// ---------------- static device scratch (allocation-free kernel_launch) ----
__device__ float g_XC[(size_t)M_MSG * 768];   // [xz | xh | r1+Ur_b] per message
__device__ float g_U [(size_t)M_MSG * 512];   // [h@Ur | h@Wzh] per message
__device__ float g_h [(size_t)M_MSG * HID];
__device__ float g_zb[(size_t)M_MSG * HID];   // z gate
__device__ float g_t1[(size_t)M_MSG * HID];   // (1-z)*sum_h
__device__ float g_sg[(size_t)M_MSG * HID];   // sum_gh
__device__ float g_mn[(size_t)NNODE * HID];   // mess_nei
__device__ float g_nv[(size_t)NNODE * HID];   // node_vec
__device__ float g_b0[768];                   // [Wz_b | Wh_b | Ur_b]
__device__ int   g_mx[M_MSG];                 // fnode[fmess[m]]
// bf16 split weights, [N,K] layout (MMA B operand = W^T), hi/lo pairs
__device__ __nv_bfloat16 g_B0h[768 * 256], g_B0l[768 * 256];   // [Wzx|Whx|Wr]^T
__device__ __nv_bfloat16 g_B1h[512 * 256], g_B1l[512 * 256];   // [Ur|Wzh]^T
__device__ __nv_bfloat16 g_BHh[256 * 256], g_BHl[256 * 256];   // Whh^T
__device__ __nv_bfloat16 g_BOh[256 * 512], g_BOl[256 * 512];   // out_w^T

// ---------------- PTX helpers ----------------------------------------------
__device__ __forceinline__ uint32_t su32(const void* p) {
    uint32_t a;
    asm("{ .reg .u64 t; cvta.to.shared.u64 t, %1; cvt.u32.u64 %0, t; }"
        : "=r"(a) : "l"(p));
    return a;
}
#if TC_OK
__device__ __forceinline__ bool elect1() {
    uint32_t p;
    asm volatile("{\n\t.reg .pred p;\n\telect.sync _|p, 0xFFFFFFFF;\n\t"
                 "selp.b32 %0, 1, 0, p;\n\t}" : "=r"(p));
    return p != 0;
}
__device__ __forceinline__ void mbar_init(uint32_t a, uint32_t cnt) {
    asm volatile("mbarrier.init.shared.b64 [%0], %1;" :: "r"(a), "r"(cnt) : "memory");
}
__device__ __forceinline__ void mbar_wait(uint32_t a, int par) {
    asm volatile(
        "{\n\t.reg .pred P;\n"
        "W%=:\n\t"
        "mbarrier.try_wait.parity.acquire.cta.shared::cta.b64 P, [%0], %1, 0x989680;\n\t"
        "@P bra.uni D%=;\n\t"
        "bra.uni W%=;\n"
        "D%=:\n\t}" :: "r"(a), "r"(par) : "memory");
}
__device__ __forceinline__ void tc_alloc(uint32_t smem_res, uint32_t ncols) {
    asm volatile("tcgen05.alloc.cta_group::1.sync.aligned.shared::cta.b32 [%0], %1;"
                 :: "r"(smem_res), "r"(ncols) : "memory");
}
__device__ __forceinline__ void tc_dealloc(uint32_t tmem, uint32_t ncols) {
    asm volatile("tcgen05.dealloc.cta_group::1.sync.aligned.b32 %0, %1;"
                 :: "r"(tmem), "r"(ncols));
}
__device__ __forceinline__ void tc_commit(uint32_t mbar) {
    asm volatile("tcgen05.commit.cta_group::1.mbarrier::arrive::one.shared::cluster.b64 [%0];"
                 :: "r"(mbar) : "memory");
}
__device__ __forceinline__ void mma_f16_ss(uint32_t d, uint64_t ad, uint64_t bd,
                                           uint32_t idesc, bool acc) {
    uint32_t en = acc ? 1u : 0u;
    asm volatile(
        "{\n\t.reg .pred p;\n\tsetp.ne.u32 p, %5, 0;\n\t"
        "tcgen05.mma.cta_group::1.kind::f16 [%0], %1, %2, %3, {%4, %4, %4, %4}, p;\n\t}"
        :: "r"(d), "l"(ad), "l"(bd), "r"(idesc), "r"(0u), "r"(en) : "memory");
}
__device__ __forceinline__ void tmem_ld32(uint32_t* r, uint32_t addr) {
    asm volatile(
        "tcgen05.ld.sync.aligned.32x32b.x32.b32 "
        "{%0,%1,%2,%3,%4,%5,%6,%7,%8,%9,%10,%11,%12,%13,%14,%15,"
        "%16,%17,%18,%19,%20,%21,%22,%23,%24,%25,%26,%27,%28,%29,%30,%31}, [%32];"
        : "=r"(r[0]), "=r"(r[1]), "=r"(r[2]), "=r"(r[3]),
          "=r"(r[4]), "=r"(r[5]), "=r"(r[6]), "=r"(r[7]),
          "=r"(r[8]), "=r"(r[9]), "=r"(r[10]), "=r"(r[11]),
          "=r"(r[12]), "=r"(r[13]), "=r"(r[14]), "=r"(r[15]),
          "=r"(r[16]), "=r"(r[17]), "=r"(r[18]), "=r"(r[19]),
          "=r"(r[20]), "=r"(r[21]), "=r"(r[22]), "=r"(r[23]),
          "=r"(r[24]), "=r"(r[25]), "=r"(r[26]), "=r"(r[27]),
          "=r"(r[28]), "=r"(r[29]), "=r"(r[30]), "=r"(r[31])
        : "r"(addr));
}
#define TC_WAIT_LD()  asm volatile("tcgen05.wait::ld.sync.aligned;" ::: "memory")
#define TC_FENCE_AFTER() asm volatile("tcgen05.fence::after_thread_sync;" ::: "memory")
#define FENCE_ASYNC() asm volatile("fence.proxy.async.shared::cta;" ::: "memory")
#endif  // TC_OK

#define SWZ(o) ((o) ^ (((o) >> 3) & 0x70))

__device__ __forceinline__ uint64_t mk_desc(uint32_t addr) {
    return (2ull << 61) | (1ull << 46) | (64ull << 32) | (1ull << 16)
         | ((uint64_t)(addr >> 4) & 0x3FFF);
}

// idesc: dtype=F32, a=BF16, b=BF16, N=256, M=128
static constexpr uint32_t IDESC =
    (1u << 4) | (1u << 7) | (1u << 10) | ((256u / 8) << 17) | ((128u / 16) << 24);

// SMEM layout (bytes from 1024-aligned base)
#define OFF_PTR   0
#define OFF_MBAR  16
#define OFF_AROW  64
#define OFF_AROW2 1088
#define OFF_TILE  4096
#define OFF_A(s, t) (OFF_TILE + ((s) * 2 + (t)) * 16384)
#define OFF_B(s, t) (OFF_TILE + 65536 + ((s) * 2 + (t)) * 32768)
#define TG_SMEM   (OFF_TILE + 65536 + 131072 + 1024)  // 201728

// ---------------- small helpers -------------------------------------------
__global__ void k_zero(float* p, int n) {
    int i = blockIdx.x * blockDim.x + threadIdx.x;
    if (i < n) p[i] = 0.f;
}

__device__ __forceinline__ void bsplit(float w, __nv_bfloat16* H, __nv_bfloat16* L, int i) {
    __nv_bfloat16 h = __float2bfloat16(w);
    H[i] = h;
    L[i] = __float2bfloat16(w - __bfloat162float(h));
}

__global__ void k_pack(const float* __restrict__ Wz, const float* __restrict__ Wh,
                       const float* __restrict__ Wr, const float* __restrict__ Ur,
                       const float* __restrict__ Ow,
                       const float* __restrict__ Wzb, const float* __restrict__ Whb,
                       const float* __restrict__ Urb,
                       const int* __restrict__ fnode, const int* __restrict__ fmess,
                       float* __restrict__ b0, int* __restrict__ mx) {
    int i = blockIdx.x * blockDim.x + threadIdx.x;
    int st = gridDim.x * blockDim.x;
    // B0: [n=768][k=256]: W0(k,n) = Wzx|Whx|Wr
    for (int t = i; t < 768 * 256; t += st) {
        int n = t / 256, k = t - n * 256;
        float w = (n < 256) ? Wz[k * 256 + n]
                : (n < 512) ? Wh[k * 256 + (n - 256)]
                            : Wr[k * 256 + (n - 512)];
        bsplit(w, g_B0h, g_B0l, t);
    }
    // B1: [n=512][k=256]: Ur | Wzh
    for (int t = i; t < 512 * 256; t += st) {
        int n = t / 256, k = t - n * 256;
        float w = (n < 256) ? Ur[k * 256 + n] : Wz[(256 + k) * 256 + (n - 256)];
        bsplit(w, g_B1h, g_B1l, t);
    }
    // BH: [n=256][k=256]: Whh
    for (int t = i; t < 256 * 256; t += st) {
        int n = t / 256, k = t - n * 256;
        bsplit(Wh[(256 + k) * 256 + n], g_BHh, g_BHl, t);
    }
    // BO: [n=256][k=512]: out_w^T
    for (int t = i; t < 256 * 512; t += st) {
        int n = t / 512, k = t - n * 512;
        bsplit(Ow[k * 256 + n], g_BOh, g_BOl, t);
    }
    for (int t = i; t < 768; t += st)
        b0[t] = (t < 256) ? Wzb[t] : (t < 512) ? Whb[t - 256] : Urb[t - 512];
    for (int t = i; t < M_MSG; t += st) mx[t] = fnode[fmess[t]];
}

__device__ __forceinline__ float sgm(float x) { return 1.0f / (1.0f + __expf(-x)); }

// Per-message neighbor gather + r/z gates. 64 threads per message (float4 lanes).
__global__ void k_gather(const int* __restrict__ mg, const float* __restrict__ h,
                         const float* __restrict__ U, const float* __restrict__ XC,
                         float* __restrict__ zp, float* __restrict__ t1p,
                         float* __restrict__ sgp) {
    int gt = blockIdx.x * blockDim.x + threadIdx.x;
    int msg = gt >> 6;
    int j = gt & 63;
    if (msg >= M_MSG) return;
    const float4* h4 = (const float4*)h;   // row stride 64
    const float4* U4 = (const float4*)U;   // row stride 128
    const float4* X4 = (const float4*)XC;  // row stride 192
    float4 xz = X4[(size_t)msg * 192 + j];
    float4 r1 = X4[(size_t)msg * 192 + 128 + j];
    float shx = 0, shy = 0, shz = 0, shw = 0;
    float zlx = xz.x, zly = xz.y, zlz = xz.z, zlw = xz.w;
    float sgx = 0, sgy = 0, sgz = 0, sgw = 0;
#pragma unroll
    for (int k = 0; k < 5; k++) {
        int gi = mg[msg * 5 + k];
        float4 hv = h4[(size_t)gi * 64 + j];
        float4 uh = U4[(size_t)gi * 128 + j];
        float4 hz = U4[(size_t)gi * 128 + 64 + j];
        shx += hv.x; shy += hv.y; shz += hv.z; shw += hv.w;
        zlx += hz.x; zly += hz.y; zlz += hz.z; zlw += hz.w;
        sgx += sgm(r1.x + uh.x) * hv.x;
        sgy += sgm(r1.y + uh.y) * hv.y;
        sgz += sgm(r1.z + uh.z) * hv.z;
        sgw += sgm(r1.w + uh.w) * hv.w;
    }
    float zx = sgm(zlx), zy = sgm(zly), zz2 = sgm(zlz), zw = sgm(zlw);
    size_t o = (size_t)msg * 64 + j;
    ((float4*)zp)[o]  = make_float4(zx, zy, zz2, zw);
    ((float4*)t1p)[o] = make_float4((1.f - zx) * shx, (1.f - zy) * shy,
                                    (1.f - zz2) * shz, (1.f - zw) * shw);
    ((float4*)sgp)[o] = make_float4(sgx, sgy, sgz, sgw);
}

// Per-node neighbor-message sum.
__global__ void k_gnode(const int* __restrict__ ng, const float* __restrict__ h,
                        float* __restrict__ mn) {
    int gt = blockIdx.x * blockDim.x + threadIdx.x;
    int n = gt >> 6;
    int j = gt & 63;
    if (n >= NNODE) return;
    const float4* h4 = (const float4*)h;
    float x = 0, y = 0, z = 0, w = 0;
#pragma unroll
    for (int k = 0; k < 5; k++) {
        int gi = ng[n * 5 + k];
        float4 hv = h4[(size_t)gi * 64 + j];
        x += hv.x; y += hv.y; z += hv.z; w += hv.w;
    }
    ((float4*)mn)[(size_t)n * 64 + j] = make_float4(x, y, z, w);
}

// Deterministic segment mean over sorted scope_ids. One block per tree.
__global__ void k_seg(const int* __restrict__ scope, const float* __restrict__ nv,
                      float* __restrict__ out) {
    int t = blockIdx.x;
    int j = threadIdx.x;
    int lo = 0, hi = NNODE;
    while (lo < hi) { int mid = (lo + hi) >> 1; if (scope[mid] < t) lo = mid + 1; else hi = mid; }
    int lo2 = lo, hi2 = NNODE;
    while (lo2 < hi2) { int mid = (lo2 + hi2) >> 1; if (scope[mid] < t + 1) lo2 = mid + 1; else hi2 = mid; }
    float s = 0.f;
    for (int r = lo; r < lo2; r++) s += nv[(size_t)r * HID + j];
    out[(size_t)t * HID + j] = s / fmaxf((float)(lo2 - lo), 1.f);
}

// ---------------- tcgen05 split-bf16 GEMM, 128x256 tile, K-chunk 64 --------
// D(128x256 fp32 in TMEM) += Ahi*Bhi + Ahi*Blo + Alo*Bhi   (3 MMAs / K16 step)
// MODE 0: A row = emb[aidx[m]] (fp32, split on load), +bias, store   (XC)
// MODE 1: plain A @ B store                                          (U)
// MODE 2: GRU combine epilogue, in-place h update
// MODE 3: A row = [emb[aidx[n]] | A2[n]] (K=512), +bias, relu        (node_vec)
struct TG {
    const float* A;
    const __nv_bfloat16* Bh; const __nv_bfloat16* Bl;
    float* C;
    int ldc;     // C row stride
    int Kb;      // B global row stride (= K)
    int nch;     // K / 64
    const float* bias;
    const int* aidx; const float* emb;
    const float* A2;
    const float* XC; const float* zv; const float* t1;
};

template <int MODE>
__global__ void __launch_bounds__(256) tgemm(TG p) {
    extern __shared__ char smraw[];
    char* sm = (char*)(((uintptr_t)smraw + 1023) & ~(uintptr_t)1023);
    uint32_t sb = su32(sm);
    (void)sb;
    const int tid = threadIdx.x;
    const int m0 = blockIdx.y * 128, n0 = blockIdx.x * 256;

    const float** Ar1 = (const float**)(sm + OFF_AROW);
    const float** Ar2 = (const float**)(sm + OFF_AROW2);
    if (tid < 128) {
        int m = m0 + tid;
        if (MODE == 0) {
            Ar1[tid] = p.emb + (size_t)__ldg(p.aidx + m) * 256;
        } else if (MODE == 3) {
            Ar1[tid] = p.emb + (size_t)__ldg(p.aidx + m) * 256;
            Ar2[tid] = p.A2 + (size_t)m * 256;
        } else {
            Ar1[tid] = p.A + (size_t)m * 256;
        }
    }

#if TC_OK
    if (tid < 32) tc_alloc(sb + OFF_PTR, 256);
    if (tid == 0) { mbar_init(sb + OFF_MBAR, 1); mbar_init(sb + OFF_MBAR + 8, 1); }
    __syncthreads();
    uint32_t tmem = *(const uint32_t*)(sm + OFF_PTR);

    int ph0 = 0, ph1 = 0;
    const int nch = p.nch;
    for (int c = 0; c < nch; c++) {
        int s = c & 1;
        if (c >= 2) {
            if (s == 0) { mbar_wait(sb + OFF_MBAR, ph0); ph0 ^= 1; }
            else        { mbar_wait(sb + OFF_MBAR + 8, ph1); ph1 ^= 1; }
        }
        // ---- stage A (fp32 -> bf16 hi/lo, SW128 swizzled)
        {
            char* Ah = sm + OFF_A(s, 0);
            char* Al = sm + OFF_A(s, 1);
            int q = tid & 15, r0 = tid >> 4;
#pragma unroll
            for (int u = 0; u < 8; u++) {
                int row = u * 16 + r0;
                const float* src;
                if (MODE == 3 && c >= 4) src = Ar2[row] + (c - 4) * 64 + q * 4;
                else                     src = Ar1[row] + c * 64 + q * 4;
                float4 a = *(const float4*)src;
                uint32_t sw = SWZ((uint32_t)(row * 128 + q * 8));
                __nv_bfloat16 h0 = __float2bfloat16(a.x);
                __nv_bfloat16 h1 = __float2bfloat16(a.y);
                __nv_bfloat16 h2 = __float2bfloat16(a.z);
                __nv_bfloat16 h3 = __float2bfloat16(a.w);
                __nv_bfloat16 l0 = __float2bfloat16(a.x - __bfloat162float(h0));
                __nv_bfloat16 l1 = __float2bfloat16(a.y - __bfloat162float(h1));
                __nv_bfloat16 l2 = __float2bfloat16(a.z - __bfloat162float(h2));
                __nv_bfloat16 l3 = __float2bfloat16(a.w - __bfloat162float(h3));
                uint2 hv, lv;
                hv.x = (uint32_t)__bfloat16_as_ushort(h0) | ((uint32_t)__bfloat16_as_ushort(h1) << 16);
                hv.y = (uint32_t)__bfloat16_as_ushort(h2) | ((uint32_t)__bfloat16_as_ushort(h3) << 16);
                lv.x = (uint32_t)__bfloat16_as_ushort(l0) | ((uint32_t)__bfloat16_as_ushort(l1) << 16);
                lv.y = (uint32_t)__bfloat16_as_ushort(l2) | ((uint32_t)__bfloat16_as_ushort(l3) << 16);
                *(uint2*)(Ah + sw) = hv;
                *(uint2*)(Al + sw) = lv;
            }
        }
        // ---- stage B (prepacked bf16 hi/lo, SW128 swizzled)
        {
            char* Bh = sm + OFF_B(s, 0);
            char* Bl = sm + OFF_B(s, 1);
            int q = tid & 7, r0 = tid >> 3;
#pragma unroll
            for (int v = 0; v < 8; v++) {
                int row = v * 32 + r0;
                size_t go = (size_t)(n0 + row) * p.Kb + c * 64 + q * 8;
                uint32_t sw = SWZ((uint32_t)(row * 128 + q * 16));
                *(uint4*)(Bh + sw) = *(const uint4*)(p.Bh + go);
                *(uint4*)(Bl + sw) = *(const uint4*)(p.Bl + go);
            }
        }
        FENCE_ASYNC();
        __syncthreads();
        if (tid < 32 && elect1()) {
            uint64_t ah = mk_desc(sb + OFF_A(s, 0));
            uint64_t al = mk_desc(sb + OFF_A(s, 1));
            uint64_t bh = mk_desc(sb + OFF_B(s, 0));
            uint64_t bl = mk_desc(sb + OFF_B(s, 1));
#pragma unroll
            for (int k = 0; k < 4; k++)
                mma_f16_ss(tmem, ah + k * 2, bh + k * 2, IDESC, (c > 0) || (k > 0));
#pragma unroll
            for (int k = 0; k < 4; k++)
                mma_f16_ss(tmem, ah + k * 2, bl + k * 2, IDESC, true);
#pragma unroll
            for (int k = 0; k < 4; k++)
                mma_f16_ss(tmem, al + k * 2, bh + k * 2, IDESC, true);
            tc_commit(sb + OFF_MBAR + (s ? 8 : 0));
        }
    }
    __syncthreads();
    mbar_wait(sb + OFF_MBAR, ph0);
    mbar_wait(sb + OFF_MBAR + 8, ph1);
    TC_FENCE_AFTER();
#else
    __syncthreads();
#endif

    // ---- epilogue: warps 0-3 cols 0..127, warps 4-7 cols 128..255
    {
        int w = tid >> 5, l = tid & 31;
        int row = (w & 3) * 32 + l;
        int m = m0 + row;
        int cb0 = (w >> 2) * 128;
#pragma unroll 1
        for (int cb = 0; cb < 128; cb += 32) {
            float rg[32];
#if TC_OK
            {
                uint32_t rr[32];
                tmem_ld32(rr, tmem + cb0 + cb);
                TC_WAIT_LD();
#pragma unroll
                for (int j = 0; j < 32; j++) rg[j] = __uint_as_float(rr[j]);
            }
#else
            // Reference-correct FFMA fallback (runs only if the plain-PTX
            // variant were ever JIT'd; sm_103a SASS is embedded so it isn't).
            {
#pragma unroll
                for (int j = 0; j < 32; j++) rg[j] = 0.f;
                int K = p.nch * 64;
                int colg = n0 + cb0 + cb;
                for (int k = 0; k < K; k++) {
                    float a = (MODE == 3 && k >= 256) ? Ar2[row][k - 256] : Ar1[row][k];
                    for (int j = 0; j < 32; j++) {
                        size_t bo = (size_t)(colg + j) * p.Kb + k;
                        float b = __bfloat162float(p.Bh[bo]) + __bfloat162float(p.Bl[bo]);
                        rg[j] += a * b;
                    }
                }
            }
#endif
            int col = n0 + cb0 + cb;
            if (MODE == 0 || MODE == 3) {
                float* dst = p.C + (size_t)m * p.ldc + col;
#pragma unroll
                for (int j = 0; j < 8; j++) {
                    float4 v;
                    v.x = rg[j * 4 + 0] + __ldg(p.bias + col + j * 4 + 0);
                    v.y = rg[j * 4 + 1] + __ldg(p.bias + col + j * 4 + 1);
                    v.z = rg[j * 4 + 2] + __ldg(p.bias + col + j * 4 + 2);
                    v.w = rg[j * 4 + 3] + __ldg(p.bias + col + j * 4 + 3);
                    if (MODE == 3) {
                        v.x = fmaxf(v.x, 0.f); v.y = fmaxf(v.y, 0.f);
                        v.z = fmaxf(v.z, 0.f); v.w = fmaxf(v.w, 0.f);
                    }
                    *(float4*)(dst + j * 4) = v;
                }
            } else if (MODE == 1) {
                float* dst = p.C + (size_t)m * p.ldc + col;
#pragma unroll
                for (int j = 0; j < 8; j++) {
                    float4 v = make_float4(rg[j * 4 + 0], rg[j * 4 + 1],
                                           rg[j * 4 + 2], rg[j * 4 + 3]);
                    *(float4*)(dst + j * 4) = v;
                }
            } else {  // MODE 2: h = (t1 + z * tanh(xh + P)) * mask
                size_t ro = (size_t)m * 256 + col;
                const float4* xh4 = (const float4*)(p.XC + (size_t)m * 768 + 256 + col);
                const float4* z4  = (const float4*)(p.zv + ro);
                const float4* t4  = (const float4*)(p.t1 + ro);
                float4* c4 = (float4*)(p.C + ro);
#pragma unroll
                for (int j = 0; j < 8; j++) {
                    float4 xh = xh4[j], zz = z4[j], tt = t4[j];
                    float4 o;
                    o.x = tt.x + zz.x * tanhf(xh.x + rg[j * 4 + 0]);
                    o.y = tt.y + zz.y * tanhf(xh.y + rg[j * 4 + 1]);
                    o.z = tt.z + zz.z * tanhf(xh.z + rg[j * 4 + 2]);
                    o.w = tt.w + zz.w * tanhf(xh.w + rg[j * 4 + 3]);
                    if (m == 0) o = make_float4(0.f, 0.f, 0.f, 0.f);
                    c4[j] = o;
                }
            }
        }
    }
#if TC_OK
    __syncthreads();
    if (tid < 32) tc_dealloc(tmem, 256);
#endif
}

// ---------------- orchestration --------------------------------------------
extern "C" void kernel_launch(void* const* d_in, const int* in_sizes, int n_in,
                              void* d_out, int out_size) {
    const int*   fnode = (const int*)d_in[0];
    const int*   fmess = (const int*)d_in[1];
    const int*   ng    = (const int*)d_in[2];
    const int*   mg    = (const int*)d_in[3];
    const int*   scope = (const int*)d_in[4];
    const float* emb   = (const float*)d_in[5];
    const float* Wz    = (const float*)d_in[6];
    const float* Wzb   = (const float*)d_in[7];
    const float* Wr    = (const float*)d_in[8];
    const float* Ur    = (const float*)d_in[9];
    const float* Urb   = (const float*)d_in[10];
    const float* Wh    = (const float*)d_in[11];
    const float* Whb   = (const float*)d_in[12];
    const float* Ow    = (const float*)d_in[13];
    const float* Ob    = (const float*)d_in[14];
    float* out = (float*)d_out;

    float *XC, *U, *h, *z, *t1, *sg, *mn, *nv, *b0; int* mx;
    __nv_bfloat16 *B0h, *B0l, *B1h, *B1l, *BHh, *BHl, *BOh, *BOl;
    cudaGetSymbolAddress((void**)&XC, g_XC);
    cudaGetSymbolAddress((void**)&U,  g_U);
    cudaGetSymbolAddress((void**)&h,  g_h);
    cudaGetSymbolAddress((void**)&z,  g_zb);
    cudaGetSymbolAddress((void**)&t1, g_t1);
    cudaGetSymbolAddress((void**)&sg, g_sg);
    cudaGetSymbolAddress((void**)&mn, g_mn);
    cudaGetSymbolAddress((void**)&nv, g_nv);
    cudaGetSymbolAddress((void**)&b0, g_b0);
    cudaGetSymbolAddress((void**)&mx, g_mx);
    cudaGetSymbolAddress((void**)&B0h, g_B0h); cudaGetSymbolAddress((void**)&B0l, g_B0l);
    cudaGetSymbolAddress((void**)&B1h, g_B1h); cudaGetSymbolAddress((void**)&B1l, g_B1l);
    cudaGetSymbolAddress((void**)&BHh, g_BHh); cudaGetSymbolAddress((void**)&BHl, g_BHl);
    cudaGetSymbolAddress((void**)&BOh, g_BOh); cudaGetSymbolAddress((void**)&BOl, g_BOl);

    cudaFuncSetAttribute(tgemm<0>, cudaFuncAttributeMaxDynamicSharedMemorySize, TG_SMEM);
    cudaFuncSetAttribute(tgemm<1>, cudaFuncAttributeMaxDynamicSharedMemorySize, TG_SMEM);
    cudaFuncSetAttribute(tgemm<2>, cudaFuncAttributeMaxDynamicSharedMemorySize, TG_SMEM);
    cudaFuncSetAttribute(tgemm<3>, cudaFuncAttributeMaxDynamicSharedMemorySize, TG_SMEM);

    int nh = M_MSG * HID;
    k_zero<<<(nh + 255) / 256, 256>>>(h, nh);
    k_pack<<<1024, 256>>>(Wz, Wh, Wr, Ur, Ow, Wzb, Whb, Urb, fnode, fmess, b0, mx);

    // XC = x @ [Wzx|Whx|Wr] + [bz|bh|Ur_b], x gathered from emb on the fly
    TG p0{}; p0.Bh = B0h; p0.Bl = B0l; p0.C = XC; p0.ldc = 768; p0.Kb = 256;
    p0.nch = 4; p0.bias = b0; p0.aidx = mx; p0.emb = emb;
    tgemm<0><<<dim3(3, M_MSG / 128), 256, TG_SMEM>>>(p0);

    for (int d = 0; d < DEPTH; d++) {
        // U = h @ [Ur | Wzh]
        TG p1{}; p1.A = h; p1.Bh = B1h; p1.Bl = B1l; p1.C = U; p1.ldc = 512;
        p1.Kb = 256; p1.nch = 4;
        tgemm<1><<<dim3(2, M_MSG / 128), 256, TG_SMEM>>>(p1);
        // neighbor gather + r/z gates
        k_gather<<<(M_MSG * 64) / 256, 256>>>(mg, h, U, XC, z, t1, sg);
        // P = sum_gh @ Whh ; h = (t1 + z*tanh(xh+P)) * mask  (in-place h)
        TG p2{}; p2.A = sg; p2.Bh = BHh; p2.Bl = BHl; p2.C = h; p2.ldc = 256;
        p2.Kb = 256; p2.nch = 4; p2.XC = XC; p2.zv = z; p2.t1 = t1;
        tgemm<2><<<dim3(1, M_MSG / 128), 256, TG_SMEM>>>(p2);
    }

    // mess_nei per node
    k_gnode<<<(NNODE * 64) / 256, 256>>>(ng, h, mn);

    // node_vec = relu([x_node | mess_nei] @ out_w + out_b)
    TG p3{}; p3.Bh = BOh; p3.Bl = BOl; p3.C = nv; p3.ldc = 256; p3.Kb = 512;
    p3.nch = 8; p3.bias = Ob; p3.aidx = fnode; p3.emb = emb; p3.A2 = mn;
    tgemm<3><<<dim3(1, NNODE / 128), 256, TG_SMEM>>>(p3);

    // segment mean (sorted scopes, deterministic)
    k_seg<<<NTREE, 256>>>(scope, nv, out);
}